// round 15
// baseline (speedup 1.0000x reference)
#include <cuda_runtime.h>
#include <cuda_bf16.h>
#include <stdint.h>

// BlankEmbedding: out[b,t,:] = emb[x[b,t]]
//   + sum_{j=1..3, t-j>=0} [x[b,t-j+1]==BLANK && x[b,t-j]!=BLANK] * emb[x[b,t-j]]
//
// B=4, S=4096, DIM=1024 (4KB rows), VOCAB=50257, BLANK=100.
//
// prepass: one thread/row -> int4 descriptor {tok, add0, add1, add2}.
// main:    TMA bulk-copy pipeline. Per row: cp.async.bulk gmem->smem
//          (raw-address 4KB gather), mbarrier complete_tx, then
//          cp.async.bulk smem->gmem bulk_group store. 888 persistent
//          1-warp blocks, 8-stage SMEM ring, lookahead 6. The DMA path
//          keeps ~150KB/SM in flight with zero RF/L1 traffic, which the
//          LDG path could never expose (R12-R14 all plateaued at ~23us
//          with every pipe under 50%). Rare blank-add rows are patched
//          in SMEM with LDG adds + fence.proxy.async before the store.

#define EB_VOCAB 50257
#define EB_DIM   1024
#define EB_ROW_BYTES 4096
#define EB_BLANK 100
#define EB_S     4096
#define EB_ROWS  16384
#define NST      8          // smem stages (8 * 4KB = 32KB)
#define LA       6          // consumer lag (== NST-2, see wait_group math)
#define GRID_MAIN (148 * 6) // ~6 blocks/SM by smem

__device__ int4 g_desc[EB_ROWS];

__device__ __forceinline__ int eb_tok(const void* __restrict__ x,
                                      int idx, bool is64) {
    if (is64) return (int)__ldg(((const long long*)x) + idx);
    return __ldg(((const int*)x) + idx);
}

// ---------------- prepass: build per-row descriptors ----------------
__global__ void __launch_bounds__(128)
blank_emb_prep(const void* __restrict__ x)
{
    const int row = blockIdx.x * 128 + threadIdx.x;
    if (row >= EB_ROWS) return;

    // dtype detection: int32 data read as int64 is >= 2^32 (or negative)
    // unless the paired token is 0; P(8 false positives) ~ (1/50257)^8 ~ 0.
    const long long* x64 = (const long long*)x;
    bool is64 = true;
#pragma unroll
    for (int i = 0; i < 8; i++) {
        long long v = __ldg(&x64[i]);
        if (v < 0 || v >= (long long)EB_VOCAB) is64 = false;
    }

    const int t    = row & (EB_S - 1);
    const int base = row & ~(EB_S - 1);

    int4 d;
    d.x = eb_tok(x, row, is64);
    d.y = -1; d.z = -1; d.w = -1;
    int* adds = &d.y;

#pragma unroll
    for (int j = 1; j <= 3; j++) {
        const int s = t - j;
        if (s >= 0) {
            if (eb_tok(x, base + s + 1, is64) == EB_BLANK) {
                const int xs = eb_tok(x, base + s, is64);
                if (xs != EB_BLANK) adds[j - 1] = xs;
            }
        }
    }
    g_desc[row] = d;
}

// ---------------- main: TMA bulk-copy pipeline ----------------
__device__ __forceinline__ uint32_t eb_s2u(const void* p) {
    return (uint32_t)__cvta_generic_to_shared(p);
}

__device__ __forceinline__ void eb_wait_parity(uint32_t m, uint32_t p) {
    asm volatile(
        "{\n\t"
        ".reg .pred P;\n\t"
        "EBW_%=:\n\t"
        "mbarrier.try_wait.parity.acquire.cta.shared::cta.b64 P, [%0], %1, 0x989680;\n\t"
        "@!P bra EBW_%=;\n\t"
        "}"
        :: "r"(m), "r"(p) : "memory");
}

__global__ void __launch_bounds__(32)
blank_emb_main(const float* __restrict__ emb,
               float* __restrict__ out)
{
    __shared__ __align__(128) float4 buf[NST][EB_DIM / 4];
    __shared__ __align__(8) unsigned long long mbar[NST];

    const int lane = threadIdx.x;

    if (lane == 0) {
#pragma unroll
        for (int s = 0; s < NST; s++) {
            asm volatile("mbarrier.init.shared.b64 [%0], 1;"
                         :: "r"(eb_s2u(&mbar[s])) : "memory");
        }
        asm volatile("fence.proxy.async.shared::cta;" ::: "memory");
    }
    __syncwarp();

    const int nrows = (EB_ROWS - blockIdx.x + gridDim.x - 1) / gridDim.x;

    for (int it = 0; it < nrows + LA; it++) {
        // ---- producer: issue bulk load for row(it) ----
        if (it < nrows && lane == 0) {
            const int row = blockIdx.x + it * gridDim.x;
            const int s   = it & (NST - 1);
            if (it >= NST) {
                // stage s's previous store was committed at iteration it-2;
                // <=1 outstanding group guarantees its smem reads finished.
                asm volatile("cp.async.bulk.wait_group.read 1;" ::: "memory");
            }
            const int tok   = __ldg(&g_desc[row].x);
            const uint32_t m = eb_s2u(&mbar[s]);
            asm volatile("mbarrier.arrive.expect_tx.shared.b64 _, [%0], %1;"
                         :: "r"(m), "r"(EB_ROW_BYTES) : "memory");
            asm volatile(
                "cp.async.bulk.shared::cta.global.mbarrier::complete_tx::bytes "
                "[%0], [%1], %2, [%3];"
                :: "r"(eb_s2u(&buf[s][0])),
                   "l"(emb + (size_t)tok * EB_DIM),
                   "r"(EB_ROW_BYTES), "r"(m)
                : "memory");
        }

        // ---- consumer: store row(it - LA) ----
        const int ci = it - LA;
        if (ci >= 0) {
            const int row = blockIdx.x + ci * gridDim.x;
            const int s   = ci & (NST - 1);
            const uint32_t phase = (ci / NST) & 1;
            const uint32_t m = eb_s2u(&mbar[s]);

            const int4 d = __ldg(&g_desc[row]);
            const bool has_add = (d.y >= 0) || (d.z >= 0) || (d.w >= 0);

            if (has_add) {
                // rare path (~1/50257 per position): patch smem buffer
                eb_wait_parity(m, phase);
                const int a[3] = {d.y, d.z, d.w};
#pragma unroll
                for (int j = 0; j < 3; j++) {
                    if (a[j] >= 0) {
                        const float4* __restrict__ src =
                            (const float4*)(emb + (size_t)a[j] * EB_DIM);
#pragma unroll
                        for (int k = 0; k < 8; k++) {
                            const int idx = lane + 32 * k;
                            const float4 e = __ldg(src + idx);
                            float4 v = buf[s][idx];
                            v.x += e.x; v.y += e.y; v.z += e.z; v.w += e.w;
                            buf[s][idx] = v;
                        }
                    }
                }
                asm volatile("fence.proxy.async.shared::cta;" ::: "memory");
                __syncwarp();
            }

            if (lane == 0) {
                if (!has_add) eb_wait_parity(m, phase);
                asm volatile(
                    "cp.async.bulk.global.shared::cta.bulk_group [%0], [%1], %2;"
                    :: "l"(out + (size_t)row * EB_DIM),
                       "r"(eb_s2u(&buf[s][0])),
                       "r"(EB_ROW_BYTES)
                    : "memory");
                asm volatile("cp.async.bulk.commit_group;" ::: "memory");
            }
        }
    }

    // smem must stay alive until all bulk stores finish reading it
    if (lane == 0)
        asm volatile("cp.async.bulk.wait_group.read 0;" ::: "memory");
}

extern "C" void kernel_launch(void* const* d_in, const int* in_sizes, int n_in,
                              void* d_out, int out_size) {
    const void*  x   = d_in[0];               // [B,S] tokens (int64 or int32)
    const float* emb = (const float*)d_in[1]; // [VOCAB, DIM] fp32
    float*       out = (float*)d_out;         // [B,S,DIM] fp32

    blank_emb_prep<<<(EB_ROWS + 127) / 128, 128>>>(x);
    blank_emb_main<<<GRID_MAIN, 32>>>(emb, out);
}